// round 11
// baseline (speedup 1.0000x reference)
#include <cuda_runtime.h>

#define NSEG 256
#define D 128

#define BLOCKS 1184                  // 148 SMs x 8 CTAs, one full wave
#define THREADS 256
#define WARPS_PER_CTA 8
#define BINS 8                       // CTA chunk (886 rows) touches <=2 segs; 8 = margin
#define TOT_SLOTS (BLOCKS * BINS)    // 9472

// ---------------------------------------------------------------------------
// CTA-level partial slots (alloc-free rule: __device__ globals). Every slot
// header is rewritten every call => no zeroing pass, no atomics, determinism.
// ---------------------------------------------------------------------------
__device__ int    g_hseg[TOT_SLOTS];        // segment id per slot
__device__ int    g_hcnt[TOT_SLOTS];        // row count (0 = empty bin)
__device__ float4 g_data[TOT_SLOTS][32];    // 128-float partial sum per slot

// ---------------------------------------------------------------------------
// Pass 1: segmented sum. Warp-level streaming chunks (the proven 81us loop),
// CTA-level merge through smem bins. Sorted ids => bin = seg - seg[CTA row 0]
// is a small non-negative index. Flushes are smem float atomics (spread-addr,
// ~2 cyc/lane, once per warp-segment); global spill is 8 plain STG.128 rows.
// ---------------------------------------------------------------------------
__global__ __launch_bounds__(THREADS, 8) void segsum_kernel(
    const float4* __restrict__ inp,   // (n, 32) float4 view of (n, 128) float
    const int* __restrict__ seg,      // (n,) sorted segment ids
    int n)
{
    __shared__ float s_bins[BINS][D];   // 4 KB
    __shared__ int   s_cnt[BINS];

    const int lane = threadIdx.x & 31;
    const int wid = threadIdx.x >> 5;
    const int c = blockIdx.x;

    // Zero bins.
    for (int i = threadIdx.x; i < BINS * D; i += THREADS)
        ((float*)s_bins)[i] = 0.0f;
    if (threadIdx.x < BINS) s_cnt[threadIdx.x] = 0;
    __syncthreads();

    const int rpc = (n + BLOCKS - 1) / BLOCKS;            // rows per CTA (886)
    const int R0 = c * rpc;
    const int R1 = min(n, R0 + rpc);
    const int first_cta = seg[min(R0, n - 1)];

    const int rpw = (rpc + WARPS_PER_CTA - 1) / WARPS_PER_CTA;  // 111
    const int r0 = R0 + wid * rpw;
    const int r1 = min(R1, r0 + rpw);

    if (r0 < r1) {
        int r = r0;
        const int first = seg[r0];
        const int last = seg[r1 - 1];
        float4 acc = make_float4(0.0f, 0.0f, 0.0f, 0.0f);

        if (first == last) {
            // ---- Uniform warp chunk (common case): streaming quad loop. ----
            while (r + 4 <= r1) {
                float4 v0 = inp[(size_t)(r + 0) * 32 + lane];
                float4 v1 = inp[(size_t)(r + 1) * 32 + lane];
                float4 v2 = inp[(size_t)(r + 2) * 32 + lane];
                float4 v3 = inp[(size_t)(r + 3) * 32 + lane];
                acc.x += (v0.x + v1.x) + (v2.x + v3.x);
                acc.y += (v0.y + v1.y) + (v2.y + v3.y);
                acc.z += (v0.z + v1.z) + (v2.z + v3.z);
                acc.w += (v0.w + v1.w) + (v2.w + v3.w);
                r += 4;
            }
            for (; r < r1; ++r) {
                float4 v = inp[(size_t)r * 32 + lane];
                acc.x += v.x; acc.y += v.y; acc.z += v.z; acc.w += v.w;
            }
            int bin = min(first - first_cta, BINS - 1);
            float* b = &s_bins[bin][lane * 4];
            atomicAdd(b + 0, acc.x);
            atomicAdd(b + 1, acc.y);
            atomicAdd(b + 2, acc.z);
            atomicAdd(b + 3, acc.w);
            if (lane == 0) atomicAdd(&s_cnt[bin], r1 - r0);
        } else {
            // ---- Boundary warp chunk (rare). -------------------------------
            int cnt = 0;
            int cur = first;
            auto flush = [&](int seg_id, const float4& a, int cn) {
                int bin = min(seg_id - first_cta, BINS - 1);
                float* b = &s_bins[bin][lane * 4];
                atomicAdd(b + 0, a.x);
                atomicAdd(b + 1, a.y);
                atomicAdd(b + 2, a.z);
                atomicAdd(b + 3, a.w);
                if (lane == 0) atomicAdd(&s_cnt[bin], cn);
            };
            while (r + 4 <= r1) {
                int s0 = seg[r];
                int s3 = seg[r + 3];
                float4 v0 = inp[(size_t)(r + 0) * 32 + lane];
                float4 v1 = inp[(size_t)(r + 1) * 32 + lane];
                float4 v2 = inp[(size_t)(r + 2) * 32 + lane];
                float4 v3 = inp[(size_t)(r + 3) * 32 + lane];
                if (s0 == cur && s3 == cur) {
                    acc.x += (v0.x + v1.x) + (v2.x + v3.x);
                    acc.y += (v0.y + v1.y) + (v2.y + v3.y);
                    acc.z += (v0.z + v1.z) + (v2.z + v3.z);
                    acc.w += (v0.w + v1.w) + (v2.w + v3.w);
                    cnt += 4;
                } else {
                    int s1 = seg[r + 1];
                    int s2 = seg[r + 2];
                    int   ss[4] = {s0, s1, s2, s3};
                    float4 vv[4] = {v0, v1, v2, v3};
                    #pragma unroll
                    for (int i = 0; i < 4; ++i) {
                        if (ss[i] != cur) {
                            flush(cur, acc, cnt);
                            acc = make_float4(0.0f, 0.0f, 0.0f, 0.0f);
                            cnt = 0;
                            cur = ss[i];
                        }
                        acc.x += vv[i].x; acc.y += vv[i].y;
                        acc.z += vv[i].z; acc.w += vv[i].w;
                        cnt++;
                    }
                }
                r += 4;
            }
            for (; r < r1; ++r) {
                int s = seg[r];
                float4 v = inp[(size_t)r * 32 + lane];
                if (s != cur) {
                    flush(cur, acc, cnt);
                    acc = make_float4(0.0f, 0.0f, 0.0f, 0.0f);
                    cnt = 0;
                    cur = s;
                }
                acc.x += v.x; acc.y += v.y; acc.z += v.z; acc.w += v.w;
                cnt++;
            }
            flush(cur, acc, cnt);
        }
    }
    __syncthreads();

    // Spill the 8 CTA bins to global slots (plain vectorized stores).
    if (wid < BINS) {
        int slot = c * BINS + wid;
        const float4* b = (const float4*)s_bins[wid];
        g_data[slot][lane] = b[lane];
        if (lane == 0) {
            int sid = first_cta + wid;
            g_hseg[slot] = (sid < NSEG) ? sid : (NSEG - 1);  // empty bins: cnt==0
            g_hcnt[slot] = s_cnt[wid];
        }
    }
}

// ---------------------------------------------------------------------------
// Pass 2: per-segment gather + mean. One CTA per segment. Branch-light,
// independent-load scan of all 9472 headers (L2-broadcast, no search), smem
// match list, warp-parallel 512B gathers, reduce, divide, write d_out
// (covers the 0xAA poison -> no zero pass needed).
// ---------------------------------------------------------------------------
__global__ __launch_bounds__(256) void finalize_kernel(float* __restrict__ out) {
    const int s = blockIdx.x;          // segment id
    const int tid = threadIdx.x;
    const int lane = tid & 31;
    const int w = tid >> 5;            // 8 warps

    __shared__ int s_list[64];
    __shared__ int s_nm;
    __shared__ int s_count;
    __shared__ float4 s_part[8][32];

    if (tid == 0) { s_nm = 0; s_count = 0; }
    __syncthreads();

    // Header scan: 9472/256 = 37 independent iterations per thread.
    for (int e = tid; e < TOT_SLOTS; e += 256) {
        int c = g_hcnt[e];
        if (c > 0 && g_hseg[e] == s) {
            int idx = atomicAdd(&s_nm, 1);
            if (idx < 64) s_list[idx] = e;
            atomicAdd(&s_count, c);
        }
    }
    __syncthreads();

    const int nm = min(s_nm, 64);
    float4 acc = make_float4(0.0f, 0.0f, 0.0f, 0.0f);
    for (int m = w; m < nm; m += 8) {
        float4 v = g_data[s_list[m]][lane];
        acc.x += v.x; acc.y += v.y; acc.z += v.z; acc.w += v.w;
    }
    s_part[w][lane] = acc;
    __syncthreads();

    if (w == 0) {
        float4 a = s_part[0][lane];
        #pragma unroll
        for (int g = 1; g < 8; ++g) {
            float4 b = s_part[g][lane];
            a.x += b.x; a.y += b.y; a.z += b.z; a.w += b.w;
        }
        int c = s_count;
        float inv = 1.0f / (float)(c < 1 ? 1 : c);
        a.x *= inv; a.y *= inv; a.z *= inv; a.w *= inv;
        ((float4*)out)[s * 32 + lane] = a;
    }
}

// ---------------------------------------------------------------------------
// Launch. d_in[0] = inp (float32, n*128), d_in[1] = batch_seg (int32, n).
// Output: (256, 128) float32 means. Two launches, no zero pass, no gmem atomics.
// ---------------------------------------------------------------------------
extern "C" void kernel_launch(void* const* d_in, const int* in_sizes, int n_in,
                              void* d_out, int out_size) {
    const float* inp = (const float*)d_in[0];
    const int* seg = (const int*)d_in[1];
    float* out = (float*)d_out;
    const int n = in_sizes[1];  // number of rows

    segsum_kernel<<<BLOCKS, THREADS>>>((const float4*)inp, seg, n);
    finalize_kernel<<<NSEG, 256>>>(out);
}

// round 15
// speedup vs baseline: 1.1533x; 1.1533x over previous
#include <cuda_runtime.h>

#define NSEG 256
#define D 128
#define OUT_ELEMS (NSEG * D)

#define BLOCKS 1184                  // 148 SMs x 8 CTAs, one full wave
#define THREADS 256
#define NWARPS (BLOCKS * (THREADS / 32))   // 9472

// ---------------------------------------------------------------------------
// Persistent accumulators (alloc-free rule: __device__ globals). Zero at
// module load; finalize_kernel resets them after reading, so every call of
// kernel_launch sees zeros -> deterministic under graph capture/replay.
// L2-resident (129 KB) -> atomic flushes are cheap REDG to hot lines.
// ---------------------------------------------------------------------------
__device__ float g_sums[NSEG * D];
__device__ int   g_counts[NSEG];

// ---------------------------------------------------------------------------
// Pass 1: segmented sum. One warp owns a contiguous row chunk; lane l holds
// float4 columns [4l, 4l+4). Sorted ids: if the chunk's first and last ids
// match, the whole chunk is one segment -> pure streaming quad loop (the
// proven 81us body). Flushes: atomicAdd into the persistent accumulator,
// once per (warp, segment) -> ~1.2M REDG total (~4us tail, measured R9/R6).
// ---------------------------------------------------------------------------
__device__ __forceinline__ void flush_acc(int seg_id, int lane,
                                          const float4& acc, int cnt) {
    float* p = g_sums + seg_id * D + lane * 4;
    atomicAdd(p + 0, acc.x);
    atomicAdd(p + 1, acc.y);
    atomicAdd(p + 2, acc.z);
    atomicAdd(p + 3, acc.w);
    if (lane == 0) atomicAdd(&g_counts[seg_id], cnt);
}

__global__ __launch_bounds__(THREADS, 8) void segsum_kernel(
    const float4* __restrict__ inp,   // (n, 32) float4 view of (n, 128) float
    const int* __restrict__ seg,      // (n,) sorted segment ids
    int n)
{
    const int lane = threadIdx.x & 31;
    const int warp_global = (blockIdx.x * blockDim.x + threadIdx.x) >> 5;

    const int rows_per_warp = (n + NWARPS - 1) / NWARPS;
    const int r0 = warp_global * rows_per_warp;
    const int r1 = min(n, r0 + rows_per_warp);
    if (r0 >= r1) return;
    int r = r0;

    const int first = seg[r0];
    const int last = seg[r1 - 1];

    float4 acc = make_float4(0.0f, 0.0f, 0.0f, 0.0f);

    if (first == last) {
        // -------- Uniform chunk (common case): streaming quad loop. ---------
        while (r + 4 <= r1) {
            float4 v0 = inp[(size_t)(r + 0) * 32 + lane];
            float4 v1 = inp[(size_t)(r + 1) * 32 + lane];
            float4 v2 = inp[(size_t)(r + 2) * 32 + lane];
            float4 v3 = inp[(size_t)(r + 3) * 32 + lane];
            acc.x += (v0.x + v1.x) + (v2.x + v3.x);
            acc.y += (v0.y + v1.y) + (v2.y + v3.y);
            acc.z += (v0.z + v1.z) + (v2.z + v3.z);
            acc.w += (v0.w + v1.w) + (v2.w + v3.w);
            r += 4;
        }
        for (; r < r1; ++r) {
            float4 v = inp[(size_t)r * 32 + lane];
            acc.x += v.x; acc.y += v.y; acc.z += v.z; acc.w += v.w;
        }
        flush_acc(first, lane, acc, r1 - r0);
    } else {
        // -------- Boundary chunk (rare, ~3% of warps). ----------------------
        int cnt = 0;
        int cur = first;
        while (r + 4 <= r1) {
            int s0 = seg[r];
            int s3 = seg[r + 3];
            float4 v0 = inp[(size_t)(r + 0) * 32 + lane];
            float4 v1 = inp[(size_t)(r + 1) * 32 + lane];
            float4 v2 = inp[(size_t)(r + 2) * 32 + lane];
            float4 v3 = inp[(size_t)(r + 3) * 32 + lane];
            if (s0 == cur && s3 == cur) {
                acc.x += (v0.x + v1.x) + (v2.x + v3.x);
                acc.y += (v0.y + v1.y) + (v2.y + v3.y);
                acc.z += (v0.z + v1.z) + (v2.z + v3.z);
                acc.w += (v0.w + v1.w) + (v2.w + v3.w);
                cnt += 4;
            } else {
                int s1 = seg[r + 1];
                int s2 = seg[r + 2];
                int   ss[4] = {s0, s1, s2, s3};
                float4 vv[4] = {v0, v1, v2, v3};
                #pragma unroll
                for (int i = 0; i < 4; ++i) {
                    if (ss[i] != cur) {
                        flush_acc(cur, lane, acc, cnt);
                        acc = make_float4(0.0f, 0.0f, 0.0f, 0.0f);
                        cnt = 0;
                        cur = ss[i];
                    }
                    acc.x += vv[i].x; acc.y += vv[i].y;
                    acc.z += vv[i].z; acc.w += vv[i].w;
                    cnt++;
                }
            }
            r += 4;
        }
        for (; r < r1; ++r) {
            int s = seg[r];
            float4 v = inp[(size_t)r * 32 + lane];
            if (s != cur) {
                flush_acc(cur, lane, acc, cnt);
                acc = make_float4(0.0f, 0.0f, 0.0f, 0.0f);
                cnt = 0;
                cur = s;
            }
            acc.x += v.x; acc.y += v.y; acc.z += v.z; acc.w += v.w;
            cnt++;
        }
        flush_acc(cur, lane, acc, cnt);
    }
}

// ---------------------------------------------------------------------------
// Pass 2: mean + reset. Reads the L2-hot accumulators, writes d_out (covers
// the 0xAA poison), and zeroes the accumulators for the next replay.
// ---------------------------------------------------------------------------
__global__ void finalize_kernel(float* __restrict__ out) {
    int i = blockIdx.x * blockDim.x + threadIdx.x;
    if (i >= OUT_ELEMS) return;
    int s = i >> 7;  // / D
    int c = g_counts[s];
    float v = g_sums[i];
    g_sums[i] = 0.0f;                       // reset for next call
    if ((i & (D - 1)) == 0) g_counts[s] = 0;
    out[i] = v / (float)(c < 1 ? 1 : c);
}

// ---------------------------------------------------------------------------
// Launch. d_in[0] = inp (float32, n*128), d_in[1] = batch_seg (int32, n).
// Output: (256, 128) float32 means. Two launches, no zero pass.
// ---------------------------------------------------------------------------
extern "C" void kernel_launch(void* const* d_in, const int* in_sizes, int n_in,
                              void* d_out, int out_size) {
    const float* inp = (const float*)d_in[0];
    const int* seg = (const int*)d_in[1];
    float* out = (float*)d_out;
    const int n = in_sizes[1];  // number of rows

    segsum_kernel<<<BLOCKS, THREADS>>>((const float4*)inp, seg, n);
    finalize_kernel<<<(OUT_ELEMS + 255) / 256, 256>>>(out);
}